// round 2
// baseline (speedup 1.0000x reference)
#include <cuda_runtime.h>
#include <math.h>

#define BB 8192
#define IND 512
#define HIDD 2048
#define NCLS 1000
#define NE 4
#define KW1 16
#define KW2 64

// ---------------- device scratch ----------------
__device__ unsigned d_xbits[BB * KW1];
__device__ unsigned d_w1b[NE * HIDD * KW1];
__device__ unsigned d_w2b[NE * HIDD * KW2];
__device__ unsigned d_w3b[NE * NCLS * KW2];
__device__ short    d_hraw[NE * BB * HIDD];       // raw GEMM outputs (reused L1/L2)
__device__ unsigned d_h1bits[NE * BB * KW2];
__device__ unsigned d_h2bits[NE * BB * KW2];
__device__ int      d_apop1[NE * BB];
__device__ int      d_apop2[NE * BB];
__device__ short    d_eo[BB * 2 * NCLS];
__device__ float    d_partial[3 * 512];
__device__ float    d_means[12];
__device__ float    d_gatew[BB * 2];
__device__ unsigned char d_slot[NE * BB];         // 0xFF unselected, else slot 0/1

// ---------------- weight mean (deterministic 2-pass) ----------------
__global__ __launch_bounds__(256) void k_reduce(const float* __restrict__ W, int n_per_e, int m) {
    int e = blockIdx.x >> 7, blk = blockIdx.x & 127;
    size_t base = (size_t)e * n_per_e;
    int chunk = (n_per_e + 127) >> 7;
    int s = blk * chunk, en = min(s + chunk, n_per_e);
    float acc = 0.f;
    for (int i = s + (int)threadIdx.x; i < en; i += 256) acc += W[base + i];
    __shared__ float red[256];
    red[threadIdx.x] = acc; __syncthreads();
    for (int st = 128; st > 0; st >>= 1) {
        if ((int)threadIdx.x < st) red[threadIdx.x] += red[threadIdx.x + st];
        __syncthreads();
    }
    if (threadIdx.x == 0) d_partial[m * 512 + blockIdx.x] = red[0];
}

__global__ void k_means() {
    int t = threadIdx.x;
    if (t >= 12) return;
    int m = t >> 2, e = t & 3;
    float s = 0.f;
    for (int i = 0; i < 128; i++) s += d_partial[m * 512 + e * 128 + i];
    float n = (m == 0) ? 2048.f * 512.f : (m == 1 ? 2048.f * 2048.f : 1000.f * 2048.f);
    d_means[t] = s / n;
}

// ---------------- bit packing ----------------
__global__ __launch_bounds__(256) void k_packw(const float* __restrict__ W, int moff,
                                               int words_per_e, int target, int total) {
    int w = blockIdx.x * 256 + threadIdx.x;
    if (w >= total) return;
    int e = w / words_per_e;
    float mu = d_means[moff + e];
    const float* p = W + (size_t)w * 32;
    unsigned bits = 0;
#pragma unroll
    for (int j = 0; j < 32; j++) bits |= (p[j] > mu) ? (1u << j) : 0u;
    unsigned* out = (target == 0) ? d_w1b : (target == 1 ? d_w2b : d_w3b);
    out[w] = bits;
}

__global__ __launch_bounds__(256) void k_packx(const float* __restrict__ x) {
    int w = blockIdx.x * 256 + threadIdx.x;
    const float* p = x + (size_t)w * 32;
    unsigned bits = 0;
#pragma unroll
    for (int j = 0; j < 32; j++) bits |= (p[j] > 0.f) ? (1u << j) : 0u;
    d_xbits[w] = bits;
}

// ---------------- fused router MLP + softmax + top2 ----------------
__global__ __launch_bounds__(256) void k_router(const float* __restrict__ x,
    const float* __restrict__ Wr1, const float* __restrict__ br1,
    const float* __restrict__ Wr2, const float* __restrict__ br2,
    const float* __restrict__ Wr3, const float* __restrict__ br3)
{
    __shared__ float buf[16 * 512];
    int b0 = blockIdx.x * 16, tid = threadIdx.x;
    for (int i = tid; i < 16 * 512; i += 256) buf[i] = x[(size_t)b0 * 512 + i];
    __syncthreads();
    float acc[16];
#pragma unroll
    for (int t = 0; t < 16; t++) acc[t] = 0.f;
    {
        const float* w = Wr1 + (size_t)tid * 512;
        for (int i = 0; i < 512; i++) {
            float wv = __ldg(w + i);
#pragma unroll
            for (int t = 0; t < 16; t++) acc[t] = fmaf(wv, buf[t * 512 + i], acc[t]);
        }
    }
    __syncthreads();
    {
        float bb = br1[tid];
#pragma unroll
        for (int t = 0; t < 16; t++) buf[t * 256 + tid] = fmaxf(acc[t] + bb, 0.f);
    }
    __syncthreads();
    if (tid < 128) {
#pragma unroll
        for (int t = 0; t < 16; t++) acc[t] = 0.f;
        const float* w = Wr2 + (size_t)tid * 256;
        for (int i = 0; i < 256; i++) {
            float wv = __ldg(w + i);
#pragma unroll
            for (int t = 0; t < 16; t++) acc[t] = fmaf(wv, buf[t * 256 + i], acc[t]);
        }
    }
    __syncthreads();
    if (tid < 128) {
        float bb = br2[tid];
#pragma unroll
        for (int t = 0; t < 16; t++) buf[4096 + t * 132 + tid] = fmaxf(acc[t] + bb, 0.f);
    }
    __syncthreads();
    if (tid < 16) {
        float s[4];
#pragma unroll
        for (int e = 0; e < 4; e++) {
            float a = br3[e];
            const float* w = Wr3 + e * 128;
            for (int i = 0; i < 128; i++) a = fmaf(w[i], buf[4096 + tid * 132 + i], a);
            s[e] = a;
        }
        float m = fmaxf(fmaxf(s[0], s[1]), fmaxf(s[2], s[3]));
        float p[4], Z = 0.f;
#pragma unroll
        for (int e = 0; e < 4; e++) { p[e] = expf(s[e] - m); Z += p[e]; }
        int i0 = 0;
        for (int e = 1; e < 4; e++) if (p[e] > p[i0]) i0 = e;
        int i1 = (i0 == 0) ? 1 : 0;
        for (int e = 0; e < 4; e++) { if (e == i0) continue; if (p[e] > p[i1]) i1 = e; }
        int b = b0 + tid;
        float g0 = p[i0] / Z, g1 = p[i1] / Z, gs = g0 + g1;
        d_gatew[b * 2] = g0 / gs; d_gatew[b * 2 + 1] = g1 / gs;
#pragma unroll
        for (int e = 0; e < 4; e++)
            d_slot[e * BB + b] = (e == i0) ? 0 : ((e == i1) ? 1 : 0xFF);
    }
}

// ---------------- layer1 binary GEMM (xor-popc, acts in {+1,-1}) ----------------
__global__ __launch_bounds__(256) void k_gemm1() {
    __shared__ uint4 as_[64 * 4];
    __shared__ unsigned char ss[64];
    int b0 = blockIdx.x * 64, o0 = blockIdx.y * 128, e = blockIdx.z;
    int tid = threadIdx.x;
    as_[tid] = ((const uint4*)d_xbits)[b0 * 4 + tid];
    if (tid < 64) ss[tid] = d_slot[e * BB + b0 + tid];
    __syncthreads();
    int o = tid & 127, t0 = (tid >> 7) * 32;
    const uint4* wr = (const uint4*)(d_w1b + ((size_t)e * HIDD + o0 + o) * KW1);
    uint4 w0 = wr[0], w1 = wr[1], w2 = wr[2], w3 = wr[3];
    short* dst = d_hraw + (size_t)e * BB * HIDD;
    for (int t = t0; t < t0 + 32; t++) {
        if (ss[t] == 0xFF) continue;
        uint4 a0 = as_[t*4+0], a1 = as_[t*4+1], a2 = as_[t*4+2], a3 = as_[t*4+3];
        int c = __popc(a0.x^w0.x)+__popc(a0.y^w0.y)+__popc(a0.z^w0.z)+__popc(a0.w^w0.w)
              + __popc(a1.x^w1.x)+__popc(a1.y^w1.y)+__popc(a1.z^w1.z)+__popc(a1.w^w1.w)
              + __popc(a2.x^w2.x)+__popc(a2.y^w2.y)+__popc(a2.z^w2.z)+__popc(a2.w^w2.w)
              + __popc(a3.x^w3.x)+__popc(a3.y^w3.y)+__popc(a3.z^w3.z)+__popc(a3.w^w3.w);
        dst[(size_t)(b0 + t) * HIDD + o0 + o] = (short)(512 - 2 * c);
    }
}

// ---------------- LayerNorm + relu + sign-pack (exact integer stats) ----------------
__global__ __launch_bounds__(256) void k_ln(const float* __restrict__ g,
                                            const float* __restrict__ bt, int phase) {
    int row = blockIdx.x;                  // e*BB + b
    if (d_slot[row] == 0xFF) return;
    int e = row / BB;
    const short* raw = d_hraw + (size_t)row * HIDD;
    int tid = threadIdx.x, lane = tid & 31, wp = tid >> 5;
    __shared__ int s_i[256];
    __shared__ long long s_q[256];
    __shared__ int spop;
    if (tid == 0) spop = 0;
    int v[8];
    int isum = 0; long long isq = 0;
#pragma unroll
    for (int it = 0; it < 8; it++) {
        int idx = it * 256 + wp * 32 + lane;
        int h = raw[idx];
        v[it] = h;
        isum += h; isq += (long long)h * h;
    }
    s_i[tid] = isum; s_q[tid] = isq;
    __syncthreads();
    for (int st = 128; st > 0; st >>= 1) {
        if (tid < st) { s_i[tid] += s_i[tid + st]; s_q[tid] += s_q[tid + st]; }
        __syncthreads();
    }
    double mu = (double)s_i[0] / 2048.0;
    double var = (double)s_q[0] / 2048.0 - mu * mu;
    float rs = (float)(1.0 / sqrt(var + 1e-5));
    float fmu = (float)mu;
    unsigned* outb = (phase == 1) ? d_h1bits : d_h2bits;
    int* outp = (phase == 1) ? d_apop1 : d_apop2;
#pragma unroll
    for (int it = 0; it < 8; it++) {
        int idx = it * 256 + wp * 32 + lane;
        float gv = g[e * HIDD + idx], bv = bt[e * HIDD + idx];
        float hn = ((float)v[it] - fmu) * rs;
        bool pred = (hn * gv + bv) > 0.f;
        unsigned w = __ballot_sync(0xffffffffu, pred);
        if (lane == 0) {
            outb[(size_t)row * KW2 + it * 8 + wp] = w;
            atomicAdd(&spop, __popc(w));
        }
    }
    __syncthreads();
    if (tid == 0) outp[row] = spop;
}

// ---------------- layer2 GEMM (and-popc, acts in {0,1}) ----------------
__global__ __launch_bounds__(256) void k_gemm2() {
    __shared__ uint4 a4s[64 * 16];
    __shared__ unsigned char ss[64];
    __shared__ int ap[64];
    int b0 = blockIdx.x * 64, o0 = blockIdx.y * 128, e = blockIdx.z;
    int tid = threadIdx.x;
    int base16 = (e * BB + b0) * 16;
#pragma unroll
    for (int r = 0; r < 4; r++) a4s[tid + 256 * r] = ((const uint4*)d_h1bits)[base16 + tid + 256 * r];
    if (tid < 64) { ss[tid] = d_slot[e * BB + b0 + tid]; ap[tid] = d_apop1[e * BB + b0 + tid]; }
    __syncthreads();
    int o = tid & 127, t0 = (tid >> 7) * 32;
    uint4 wreg[16];
    const uint4* wr = (const uint4*)(d_w2b + ((size_t)e * HIDD + o0 + o) * KW2);
#pragma unroll
    for (int k = 0; k < 16; k++) wreg[k] = wr[k];
    short* dst = d_hraw + (size_t)e * BB * HIDD;
    for (int t = t0; t < t0 + 32; t++) {
        if (ss[t] == 0xFF) continue;
        int acc = 0;
#pragma unroll
        for (int k = 0; k < 16; k++) {
            uint4 av = a4s[t * 16 + k];
            acc += __popc(av.x & wreg[k].x) + __popc(av.y & wreg[k].y)
                 + __popc(av.z & wreg[k].z) + __popc(av.w & wreg[k].w);
        }
        dst[(size_t)(b0 + t) * HIDD + o0 + o] = (short)(2 * acc - ap[t]);
    }
}

// ---------------- layer3 GEMM -> per-slot dots ----------------
__global__ __launch_bounds__(256) void k_gemm3() {
    __shared__ uint4 a4s[64 * 16];
    __shared__ unsigned char ss[64];
    __shared__ int ap[64];
    int b0 = blockIdx.x * 64, c0 = blockIdx.y * 128, e = blockIdx.z;
    int tid = threadIdx.x;
    int base16 = (e * BB + b0) * 16;
#pragma unroll
    for (int r = 0; r < 4; r++) a4s[tid + 256 * r] = ((const uint4*)d_h2bits)[base16 + tid + 256 * r];
    if (tid < 64) { ss[tid] = d_slot[e * BB + b0 + tid]; ap[tid] = d_apop2[e * BB + b0 + tid]; }
    __syncthreads();
    int c = c0 + (tid & 127), t0 = (tid >> 7) * 32;
    if (c >= NCLS) return;
    uint4 wreg[16];
    const uint4* wr = (const uint4*)(d_w3b + ((size_t)e * NCLS + c) * KW2);
#pragma unroll
    for (int k = 0; k < 16; k++) wreg[k] = wr[k];
    for (int t = t0; t < t0 + 32; t++) {
        if (ss[t] == 0xFF) continue;
        int acc = 0;
#pragma unroll
        for (int k = 0; k < 16; k++) {
            uint4 av = a4s[t * 16 + k];
            acc += __popc(av.x & wreg[k].x) + __popc(av.y & wreg[k].y)
                 + __popc(av.z & wreg[k].z) + __popc(av.w & wreg[k].w);
        }
        d_eo[((size_t)(b0 + t) * 2 + ss[t]) * NCLS + c] = (short)(2 * acc - ap[t]);
    }
}

// ---------------- gate combine ----------------
__global__ __launch_bounds__(256) void k_combine(float* __restrict__ out) {
    int i = blockIdx.x * 256 + threadIdx.x;     // BB*NCLS total
    int b = i / NCLS, c = i - b * NCLS;
    float g0 = d_gatew[b * 2], g1 = d_gatew[b * 2 + 1];
    out[i] = g0 * (float)d_eo[((size_t)b * 2) * NCLS + c]
           + g1 * (float)d_eo[((size_t)b * 2 + 1) * NCLS + c];
}

extern "C" void kernel_launch(void* const* d_in, const int* in_sizes, int n_in,
                              void* d_out, int out_size) {
    const float* x   = (const float*)d_in[0];
    const float* Wr1 = (const float*)d_in[1];
    const float* br1 = (const float*)d_in[2];
    const float* Wr2 = (const float*)d_in[3];
    const float* br2 = (const float*)d_in[4];
    const float* Wr3 = (const float*)d_in[5];
    const float* br3 = (const float*)d_in[6];
    const float* W1  = (const float*)d_in[7];
    const float* g1  = (const float*)d_in[8];
    const float* b1  = (const float*)d_in[9];
    const float* W2  = (const float*)d_in[10];
    const float* g2  = (const float*)d_in[11];
    const float* b2  = (const float*)d_in[12];
    const float* W3  = (const float*)d_in[13];
    float* out = (float*)d_out;

    k_reduce<<<512, 256>>>(W1, HIDD * IND, 0);
    k_reduce<<<512, 256>>>(W2, HIDD * HIDD, 1);
    k_reduce<<<512, 256>>>(W3, NCLS * HIDD, 2);
    k_means<<<1, 32>>>();
    k_packw<<<(NE * HIDD * KW1 + 255) / 256, 256>>>(W1, 0, HIDD * KW1, 0, NE * HIDD * KW1);
    k_packw<<<(NE * HIDD * KW2 + 255) / 256, 256>>>(W2, 4, HIDD * KW2, 1, NE * HIDD * KW2);
    k_packw<<<(NE * NCLS * KW2 + 255) / 256, 256>>>(W3, 8, NCLS * KW2, 2, NE * NCLS * KW2);
    k_packx<<<(BB * KW1 + 255) / 256, 256>>>(x);
    k_router<<<BB / 16, 256>>>(x, Wr1, br1, Wr2, br2, Wr3, br3);
    k_gemm1<<<dim3(BB / 64, HIDD / 128, NE), 256>>>();
    k_ln<<<NE * BB, 256>>>(g1, b1, 1);
    k_gemm2<<<dim3(BB / 64, HIDD / 128, NE), 256>>>();
    k_ln<<<NE * BB, 256>>>(g2, b2, 2);
    k_gemm3<<<dim3(BB / 64, (NCLS + 127) / 128, NE), 256>>>();
    k_combine<<<(BB * NCLS) / 256, 256>>>(out);
}